// round 17
// baseline (speedup 1.0000x reference)
#include <cuda_runtime.h>
#include <cuda_bf16.h>
#include <cuda_fp16.h>
#include <cstdint>
#include <math.h>

#define BN_EPS 1e-3f

static constexpr int BATCH = 2;
static constexpr int NTOK  = 4096;
static constexpr int CH    = 128;
static constexpr int ROWS  = BATCH * NTOK;
static constexpr float SM_SCALE = 0.08838834764831845f;
static constexpr float LOG2E    = 1.4426950408889634f;

__device__ float          g_xn [ROWS * CH];
__device__ __nv_bfloat16  g_xnh[ROWS * CH];
__device__ uint8_t        g_q8 [ROWS * CH];             // e4m3 q * SM_SCALE * LOG2E
__device__ uint8_t        g_k8 [ROWS * CH];             // e4m3 k
__device__ uint32_t       g_vt8[BATCH * CH * (NTOK/4)]; // V^T e4m3 quad-packed [b][c][tok/4]
__device__ __nv_bfloat16  g_oh [ROWS * CH];
__device__ __nv_bfloat16  g_wt [4 * CH * CH];           // wt[n][k] = W[k][n]

// ---------------------------------------------------------------------------
__device__ __forceinline__ void mma16816(float* c, const uint32_t* a, uint32_t b0, uint32_t b1) {
    asm volatile("mma.sync.aligned.m16n8k16.row.col.f32.bf16.bf16.f32 "
        "{%0,%1,%2,%3}, {%4,%5,%6,%7}, {%8,%9}, {%0,%1,%2,%3};"
        : "+f"(c[0]), "+f"(c[1]), "+f"(c[2]), "+f"(c[3])
        : "r"(a[0]), "r"(a[1]), "r"(a[2]), "r"(a[3]), "r"(b0), "r"(b1));
}
__device__ __forceinline__ void mma16832q(float* c, const uint32_t* a, uint32_t b0, uint32_t b1) {
    asm volatile("mma.sync.aligned.m16n8k32.row.col.f32.e4m3.e4m3.f32 "
        "{%0,%1,%2,%3}, {%4,%5,%6,%7}, {%8,%9}, {%0,%1,%2,%3};"
        : "+f"(c[0]), "+f"(c[1]), "+f"(c[2]), "+f"(c[3])
        : "r"(a[0]), "r"(a[1]), "r"(a[2]), "r"(a[3]), "r"(b0), "r"(b1));
}
__device__ __forceinline__ void ldsm_x4(uint32_t& r0, uint32_t& r1, uint32_t& r2, uint32_t& r3, uint32_t a) {
    asm volatile("ldmatrix.sync.aligned.m8n8.x4.shared.b16 {%0,%1,%2,%3}, [%4];"
        : "=r"(r0), "=r"(r1), "=r"(r2), "=r"(r3) : "r"(a));
}
__device__ __forceinline__ uint32_t packbf(float lo, float hi) {
    uint32_t r; asm("cvt.rn.bf16x2.f32 %0, %1, %2;" : "=r"(r) : "f"(hi), "f"(lo)); return r;
}
__device__ __forceinline__ uint32_t packf16(float lo, float hi) {
    uint32_t r; asm("cvt.rn.f16x2.f32 %0, %1, %2;" : "=r"(r) : "f"(hi), "f"(lo)); return r;
}
__device__ __forceinline__ uint32_t ex2h2(uint32_t a) {
    uint32_t r; asm("ex2.approx.f16x2 %0, %1;" : "=r"(r) : "r"(a)); return r;
}
__device__ __forceinline__ uint16_t e4m3x2_f32(float lo, float hi) {
    uint16_t r; asm("cvt.rn.satfinite.e4m3x2.f32 %0, %1, %2;" : "=h"(r) : "f"(hi), "f"(lo)); return r;
}
__device__ __forceinline__ uint32_t e4m3x2_h2(uint32_t h2) {
    uint16_t r; asm("cvt.rn.satfinite.e4m3x2.f16x2 %0, %1;" : "=h"(r) : "r"(h2)); return (uint32_t)r;
}
__device__ __forceinline__ void cp16(uint32_t dst, const void* src) {
    asm volatile("cp.async.cg.shared.global [%0], [%1], 16;" :: "r"(dst), "l"(src));
}
__device__ __forceinline__ void cp_commit() { asm volatile("cp.async.commit_group;"); }
template<int N> __device__ __forceinline__ void cp_wait() { asm volatile("cp.async.wait_group %0;" :: "n"(N)); }
__device__ __forceinline__ void group_bar(int id) {
    asm volatile("bar.sync %0, %1;" :: "r"(id), "r"(128) : "memory");
}

// ---------------------------------------------------------------------------
__global__ void bn_kernel(const float* __restrict__ x, const float* __restrict__ gamma,
                          const float* __restrict__ beta, const float* __restrict__ mmean,
                          const float* __restrict__ mvar) {
    int vi = blockIdx.x * blockDim.x + threadIdx.x;
    if (vi >= ROWS * CH / 4) return;
    int c0 = (vi & (CH/4 - 1)) * 4;
    float4 xv = reinterpret_cast<const float4*>(x)[vi];
    float4 o;
    { float s = gamma[c0+0] * rsqrtf(mvar[c0+0] + BN_EPS); o.x = (xv.x - mmean[c0+0]) * s + beta[c0+0]; }
    { float s = gamma[c0+1] * rsqrtf(mvar[c0+1] + BN_EPS); o.y = (xv.y - mmean[c0+1]) * s + beta[c0+1]; }
    { float s = gamma[c0+2] * rsqrtf(mvar[c0+2] + BN_EPS); o.z = (xv.z - mmean[c0+2]) * s + beta[c0+2]; }
    { float s = gamma[c0+3] * rsqrtf(mvar[c0+3] + BN_EPS); o.w = (xv.w - mmean[c0+3]) * s + beta[c0+3]; }
    reinterpret_cast<float4*>(g_xn)[vi] = o;
    reinterpret_cast<uint2*>(g_xnh)[vi] = make_uint2(packbf(o.x, o.y), packbf(o.z, o.w));
}

__global__ void wprep_kernel(const float* __restrict__ Wq, const float* __restrict__ Wk,
                             const float* __restrict__ Wv, const float* __restrict__ Wp) {
    int i = blockIdx.x * 256 + threadIdx.x;
    int which = i >> 14, k = (i >> 7) & 127, n = i & 127;
    const float* W = (which == 0) ? Wq : (which == 1) ? Wk : (which == 2) ? Wv : Wp;
    g_wt[which * 16384 + n * 128 + k] = __float2bfloat16(W[k * 128 + n]);
}

// ---------------------------------------------------------------------------
// mma GEMM: out[64 x 128] = A[64 x 128] @ W[128 x 128] (+ bias)
// ---------------------------------------------------------------------------
static constexpr int WT_STRIDE = 136;
static constexpr int ST_STRIDE = 134;
static constexpr int GEMM_SMEM = 128*WT_STRIDE*2 + 64*ST_STRIDE*2;

struct GemmAcc { float a[16][4]; uint32_t qa[8][4]; };

__device__ __forceinline__ void gemm_mma_core(
    const __nv_bfloat16* __restrict__ Ag, const __nv_bfloat16* Wts, int lane, int g, int tg, GemmAcc& R)
{
    #pragma unroll
    for (int kc = 0; kc < 8; ++kc) {
        R.qa[kc][0] = *(const uint32_t*)(Ag + (g    )*128 + kc*16 + tg*2);
        R.qa[kc][1] = *(const uint32_t*)(Ag + (g + 8)*128 + kc*16 + tg*2);
        R.qa[kc][2] = *(const uint32_t*)(Ag + (g    )*128 + kc*16 + 8 + tg*2);
        R.qa[kc][3] = *(const uint32_t*)(Ag + (g + 8)*128 + kc*16 + 8 + tg*2);
    }
    #pragma unroll
    for (int nt = 0; nt < 16; ++nt)
        #pragma unroll
        for (int j = 0; j < 4; ++j) R.a[nt][j] = 0.f;
    uint32_t wbase = (uint32_t)__cvta_generic_to_shared(Wts);
    uint32_t row_off = (lane & 7)*(WT_STRIDE*2) + (lane >> 3)*16;
    #pragma unroll
    for (int kc2 = 0; kc2 < 4; ++kc2)
        #pragma unroll
        for (int ntc = 0; ntc < 4; ++ntc) {
            uint32_t B[4][4];
            #pragma unroll
            for (int j = 0; j < 4; ++j)
                ldsm_x4(B[j][0], B[j][1], B[j][2], B[j][3],
                        wbase + (ntc*4+j)*8*(WT_STRIDE*2) + kc2*64 + row_off);
            #pragma unroll
            for (int h = 0; h < 2; ++h)
                #pragma unroll
                for (int j = 0; j < 4; ++j)
                    mma16816(R.a[ntc*4+j], R.qa[kc2*2+h], B[j][2*h], B[j][2*h+1]);
        }
}

__device__ __forceinline__ void load_wt_smem(const __nv_bfloat16* __restrict__ Wt,
                                             __nv_bfloat16* Wts, int tid) {
    #pragma unroll
    for (int it = 0; it < 16; ++it) {
        int idx = tid + it*128;
        *reinterpret_cast<uint4*>(Wts + (idx >> 4)*WT_STRIDE + (idx & 15)*8) =
            reinterpret_cast<const uint4*>(Wt)[idx];
    }
}

__global__ void __launch_bounds__(128) qkv_mma_kernel(
    const float* __restrict__ bq, const float* __restrict__ bk, const float* __restrict__ bv)
{
    extern __shared__ char smraw[];
    __nv_bfloat16* Wts = (__nv_bfloat16*)smraw;
    __nv_bfloat16* st  = (__nv_bfloat16*)(smraw + 128*WT_STRIDE*2);
    const int tid = threadIdx.x, lane = tid & 31, w = tid >> 5;
    const int g = lane >> 2, tg = lane & 3;
    const int which = blockIdx.y, rowBase = blockIdx.x * 64;
    const float* bias = (which == 0) ? bq : (which == 1) ? bk : bv;

    load_wt_smem(g_wt + which*16384, Wts, tid);
    __syncthreads();
    GemmAcc R;
    gemm_mma_core(g_xnh + (rowBase + w*16)*128, Wts, lane, g, tg, R);

    float b0r[16], b1r[16];
    #pragma unroll
    for (int nt = 0; nt < 16; ++nt) { b0r[nt] = bias[nt*8 + tg*2]; b1r[nt] = bias[nt*8 + tg*2 + 1]; }

    if (which < 2) {
        float sc = (which == 0) ? SM_SCALE * LOG2E : 1.f;
        uint8_t* out = (which == 0) ? g_q8 : g_k8;
        int r0 = rowBase + w*16 + g, r1 = r0 + 8;
        #pragma unroll
        for (int nt = 0; nt < 16; ++nt) {
            uint16_t lo = e4m3x2_f32((R.a[nt][0] + b0r[nt]) * sc, (R.a[nt][1] + b1r[nt]) * sc);
            uint16_t hi = e4m3x2_f32((R.a[nt][2] + b0r[nt]) * sc, (R.a[nt][3] + b1r[nt]) * sc);
            *(uint16_t*)(out + r0*128 + nt*8 + tg*2) = lo;
            *(uint16_t*)(out + r1*128 + nt*8 + tg*2) = hi;
        }
    } else {
        #pragma unroll
        for (int nt = 0; nt < 16; ++nt) {
            st[(w*16 + g    )*ST_STRIDE + nt*8 + tg*2    ] = __float2bfloat16(R.a[nt][0] + b0r[nt]);
            st[(w*16 + g    )*ST_STRIDE + nt*8 + tg*2 + 1] = __float2bfloat16(R.a[nt][1] + b1r[nt]);
            st[(w*16 + g + 8)*ST_STRIDE + nt*8 + tg*2    ] = __float2bfloat16(R.a[nt][2] + b0r[nt]);
            st[(w*16 + g + 8)*ST_STRIDE + nt*8 + tg*2 + 1] = __float2bfloat16(R.a[nt][3] + b1r[nt]);
        }
        __syncthreads();
        int by = rowBase >> 12, tokBase = rowBase & (NTOK - 1);
        #pragma unroll
        for (int it = 0; it < 16; ++it) {
            int i = tid + it*128;           // 2048 u32 words
            int kk = i & 15, c = i >> 4;    // kk: quad of keys, c: channel
            float f0 = __bfloat162float(st[(4*kk+0)*ST_STRIDE + c]);
            float f1 = __bfloat162float(st[(4*kk+1)*ST_STRIDE + c]);
            float f2 = __bfloat162float(st[(4*kk+2)*ST_STRIDE + c]);
            float f3 = __bfloat162float(st[(4*kk+3)*ST_STRIDE + c]);
            uint32_t v = (uint32_t)e4m3x2_f32(f0, f1) | ((uint32_t)e4m3x2_f32(f2, f3) << 16);
            g_vt8[(by*128 + c)*(NTOK/4) + (tokBase >> 2) + kk] = v;
        }
    }
}

__global__ void __launch_bounds__(128) proj_mma_kernel(const float* __restrict__ bp, float* __restrict__ out)
{
    extern __shared__ char smraw[];
    __nv_bfloat16* Wts = (__nv_bfloat16*)smraw;
    const int tid = threadIdx.x, lane = tid & 31, w = tid >> 5;
    const int g = lane >> 2, tg = lane & 3;
    const int rowBase = blockIdx.x * 64;
    load_wt_smem(g_wt + 3*16384, Wts, tid);
    __syncthreads();
    GemmAcc R;
    gemm_mma_core(g_oh + (rowBase + w*16)*128, Wts, lane, g, tg, R);
    #pragma unroll
    for (int nt = 0; nt < 16; ++nt) {
        float bb0 = bp[nt*8 + tg*2], bb1 = bp[nt*8 + tg*2 + 1];
        int r0 = rowBase + w*16 + g, r1 = r0 + 8;
        *reinterpret_cast<float2*>(out + r0*128 + nt*8 + tg*2) =
            make_float2(R.a[nt][0] + bb0 + g_xn[r0*128 + nt*8 + tg*2],
                        R.a[nt][1] + bb1 + g_xn[r0*128 + nt*8 + tg*2 + 1]);
        *reinterpret_cast<float2*>(out + r1*128 + nt*8 + tg*2) =
            make_float2(R.a[nt][2] + bb0 + g_xn[r1*128 + nt*8 + tg*2],
                        R.a[nt][3] + bb1 + g_xn[r1*128 + nt*8 + tg*2 + 1]);
    }
}

// ---------------------------------------------------------------------------
// FP8 flash attention, 4-way split-KV, triple-buffered cp.async.
// K rows 144B-padded e4m3; V^T rows 48B-padded quad-packed e4m3.
// ---------------------------------------------------------------------------
static constexpr int K8STR = 144;             // bytes per key row (128+16)
static constexpr int V8STR = 12;              // u32 per channel row (8+4)
static constexpr int KB8   = 32 * K8STR;      // 4608
static constexpr int VB8   = 128 * V8STR * 4; // 6144
static constexpr int BUF8  = KB8 + VB8;       // 10752
static constexpr int GRP8  = 3 * BUF8;        // 32256
static constexpr int PARKSTR = 33792;         // 32KB o + 1KB l per parked group
static constexpr int ATTN_SMEM = 4 * GRP8;    // 129024

__global__ void __launch_bounds__(512) attn_mma_kernel()
{
    extern __shared__ char smraw[];
    const int tid  = threadIdx.x;
    const int lane = tid & 31;
    const int w    = tid >> 5;
    const int gid  = w >> 2;
    const int tidg = tid & 127;
    const int g    = lane >> 2;
    const int tg   = lane & 3;
    const int by   = blockIdx.y;
    const int q0   = blockIdx.x * 64;

    const uint8_t*  Kbase = g_k8 + by*NTOK*128;
    const uint32_t* Vbase = g_vt8 + by*128*(NTOK/4);
    uint32_t smem_u32 = (uint32_t)__cvta_generic_to_shared(smraw);

    auto issue_tile = [&](int kt, int buf) {   // kt in 32-key tiles
        uint32_t kd = smem_u32 + gid*GRP8 + buf*BUF8;
        const uint8_t* Kg = Kbase + kt*32*128;
        #pragma unroll
        for (int it = 0; it < 2; ++it) {
            int idx = tidg + it*128;          // 256 chunks of 16B
            cp16(kd + (idx >> 3)*K8STR + (idx & 7)*16, Kg + (idx >> 3)*128 + (idx & 7)*16);
        }
        uint32_t vd = kd + KB8;
        #pragma unroll
        for (int it = 0; it < 2; ++it) {
            int idx = tidg + it*128;          // 256 chunks
            int c = idx >> 1, q = idx & 1;
            cp16(vd + c*(V8STR*4) + q*16, Vbase + c*(NTOK/4) + kt*8 + q*4);
        }
    };

    // persistent fp8 Q fragments (pre-scaled by SM_SCALE*LOG2E): 16 regs
    const uint8_t* Qg = g_q8 + (by*NTOK + q0 + (w & 3)*16) * 128;
    uint32_t qa[4][4];
    #pragma unroll
    for (int kc = 0; kc < 4; ++kc) {
        qa[kc][0] = *(const uint32_t*)(Qg + (g    )*128 + kc*32 + tg*4);
        qa[kc][1] = *(const uint32_t*)(Qg + (g + 8)*128 + kc*32 + tg*4);
        qa[kc][2] = *(const uint32_t*)(Qg + (g    )*128 + kc*32 + 16 + tg*4);
        qa[kc][3] = *(const uint32_t*)(Qg + (g + 8)*128 + kc*32 + 16 + tg*4);
    }

    const int loL = (lane & ~3) | ((tg & 1) << 1);
    const int hiL = loL | 1;
    const uint32_t selA = (tg >> 1) ? 0x7632u : 0x5410u;

    float o[16][4];
    #pragma unroll
    for (int n = 0; n < 16; ++n)
        #pragma unroll
        for (int j = 0; j < 4; ++j) o[n][j] = 0.f;
    float l0 = 0.f, l1 = 0.f;

    issue_tile(gid, 0);          cp_commit();
    issue_tile(4 + gid, 1);      cp_commit();

    int buf = 0;
    for (int i = 0; i < 32; ++i) {
        cp_wait<1>();
        group_bar(1 + gid);
        if (i < 30) issue_tile(4*(i + 2) + gid, (i + 2) % 3);
        cp_commit();

        const char* kb = smraw + gid*GRP8 + buf*BUF8;
        const uint32_t* Vs = (const uint32_t*)(kb + KB8);

        // ---- S = Q @ K^T (fp8 k32) ----
        float s[4][4];
        #pragma unroll
        for (int n = 0; n < 4; ++n)
            #pragma unroll
            for (int j = 0; j < 4; ++j) s[n][j] = 0.f;
        #pragma unroll
        for (int kc = 0; kc < 4; ++kc)
            #pragma unroll
            for (int n = 0; n < 4; ++n) {
                uint32_t b0 = *(const uint32_t*)(kb + (n*8+g)*K8STR + kc*32 + tg*4);
                uint32_t b1 = *(const uint32_t*)(kb + (n*8+g)*K8STR + kc*32 + 16 + tg*4);
                mma16832q(s[n], qa[kc], b0, b1);
            }

        // ---- softmax 2^s (f16x2), sum l, convert to e4m3 ----
        uint32_t hg[4], hf[4];
        #pragma unroll
        for (int nb = 0; nb < 4; ++nb) {
            hg[nb] = ex2h2(packf16(s[nb][0], s[nb][1]));   // rows g
            hf[nb] = ex2h2(packf16(s[nb][2], s[nb][3]));   // rows g+8
        }
        {
            __half2 a0 = __hadd2(__hadd2(*(__half2*)&hg[0], *(__half2*)&hg[1]),
                                 __hadd2(*(__half2*)&hg[2], *(__half2*)&hg[3]));
            l0 += __low2float(a0) + __high2float(a0);
            __half2 a1 = __hadd2(__hadd2(*(__half2*)&hf[0], *(__half2*)&hf[1]),
                                 __hadd2(*(__half2*)&hf[2], *(__half2*)&hf[3]));
            l1 += __low2float(a1) + __high2float(a1);
        }
        uint32_t e01 = e4m3x2_h2(hg[0]) | (e4m3x2_h2(hg[1]) << 16);
        uint32_t e23 = e4m3x2_h2(hg[2]) | (e4m3x2_h2(hg[3]) << 16);
        uint32_t f01 = e4m3x2_h2(hf[0]) | (e4m3x2_h2(hf[1]) << 16);
        uint32_t f23 = e4m3x2_h2(hf[2]) | (e4m3x2_h2(hf[3]) << 16);

        // ---- regroup C-frag bytes into fp8 A-fragments (8 shuffles) ----
        uint32_t pa[4];
        pa[0] = __byte_perm(__shfl_sync(0xffffffffu, e01, loL),
                            __shfl_sync(0xffffffffu, e01, hiL), selA);
        pa[1] = __byte_perm(__shfl_sync(0xffffffffu, f01, loL),
                            __shfl_sync(0xffffffffu, f01, hiL), selA);
        pa[2] = __byte_perm(__shfl_sync(0xffffffffu, e23, loL),
                            __shfl_sync(0xffffffffu, e23, hiL), selA);
        pa[3] = __byte_perm(__shfl_sync(0xffffffffu, f23, loL),
                            __shfl_sync(0xffffffffu, f23, hiL), selA);

        // ---- O += P @ V (fp8 k32, 16 independent accumulators) ----
        #pragma unroll
        for (int dt = 0; dt < 16; ++dt) {
            uint32_t b0 = Vs[(dt*8+g)*V8STR + tg];
            uint32_t b1 = Vs[(dt*8+g)*V8STR + 4 + tg];
            mma16832q(o[dt], pa, b0, b1);
        }
        buf = (buf + 1 == 3) ? 0 : buf + 1;
    }

    l0 += __shfl_xor_sync(0xffffffffu, l0, 1);
    l0 += __shfl_xor_sync(0xffffffffu, l0, 2);
    l1 += __shfl_xor_sync(0xffffffffu, l1, 1);
    l1 += __shfl_xor_sync(0xffffffffu, l1, 2);

    // park regions overlap other groups' buffers -> sync BEFORE parking
    __syncthreads();
    if (gid != 0) {
        float* So = (float*)(smraw + (gid-1)*PARKSTR);
        float* Sl = (float*)(smraw + (gid-1)*PARKSTR + 32768);
        #pragma unroll
        for (int n = 0; n < 16; ++n)
            *reinterpret_cast<float4*>(So + tidg*64 + n*4) =
                make_float4(o[n][0], o[n][1], o[n][2], o[n][3]);
        Sl[tidg*2]     = l0;
        Sl[tidg*2 + 1] = l1;
    }
    __syncthreads();
    if (gid == 0) {
        #pragma unroll
        for (int j = 0; j < 3; ++j) {
            const float* So = (const float*)(smraw + j*PARKSTR);
            const float* Sl = (const float*)(smraw + j*PARKSTR + 32768);
            l0 += Sl[tidg*2];
            l1 += Sl[tidg*2 + 1];
            #pragma unroll
            for (int n = 0; n < 16; ++n) {
                float4 b = *reinterpret_cast<const float4*>(So + tidg*64 + n*4);
                o[n][0] += b.x; o[n][1] += b.y; o[n][2] += b.z; o[n][3] += b.w;
            }
        }
        float il0 = 1.f / l0, il1 = 1.f / l1;
        __nv_bfloat16* Og = g_oh + (by*NTOK + q0 + (w & 3)*16) * 128;
        #pragma unroll
        for (int n = 0; n < 16; ++n) {
            uint32_t lo = packbf(o[n][0]*il0, o[n][1]*il0);
            uint32_t hi = packbf(o[n][2]*il1, o[n][3]*il1);
            *(uint32_t*)(Og + (g    )*128 + n*8 + tg*2) = lo;
            *(uint32_t*)(Og + (g + 8)*128 + n*8 + tg*2) = hi;
        }
    }
}

// ---------------------------------------------------------------------------
extern "C" void kernel_launch(void* const* d_in, const int* in_sizes, int n_in,
                              void* d_out, int out_size)
{
    const float* x     = (const float*)d_in[0];
    const float* gamma = (const float*)d_in[1];
    const float* beta  = (const float*)d_in[2];
    const float* mmean = (const float*)d_in[3];
    const float* mvar  = (const float*)d_in[4];
    const float* Wq    = (const float*)d_in[5];
    const float* bq    = (const float*)d_in[6];
    const float* Wk    = (const float*)d_in[7];
    const float* bk    = (const float*)d_in[8];
    const float* Wv    = (const float*)d_in[9];
    const float* bv    = (const float*)d_in[10];
    const float* Wp    = (const float*)d_in[11];
    const float* bp    = (const float*)d_in[12];
    float* out = (float*)d_out;

    cudaFuncSetAttribute(qkv_mma_kernel,  cudaFuncAttributeMaxDynamicSharedMemorySize, GEMM_SMEM);
    cudaFuncSetAttribute(proj_mma_kernel, cudaFuncAttributeMaxDynamicSharedMemorySize, GEMM_SMEM);
    cudaFuncSetAttribute(attn_mma_kernel, cudaFuncAttributeMaxDynamicSharedMemorySize, ATTN_SMEM);

    bn_kernel<<<(ROWS*CH/4 + 255)/256, 256>>>(x, gamma, beta, mmean, mvar);
    wprep_kernel<<<4*CH*CH/256, 256>>>(Wq, Wk, Wv, Wp);

    dim3 gq(ROWS/64, 3);
    qkv_mma_kernel<<<gq, 128, GEMM_SMEM>>>(bq, bk, bv);

    dim3 ga(NTOK/64, BATCH);
    attn_mma_kernel<<<ga, 512, ATTN_SMEM>>>();

    proj_mma_kernel<<<ROWS/64, 128, GEMM_SMEM>>>(bp, out);
}